// round 1
// baseline (speedup 1.0000x reference)
#include <cuda_runtime.h>
#include <cuda_bf16.h>
#include <math.h>

#define Bc 4
#define Lc 2048
#define Dc 512
#define Hc 8
#define HDc 64
#define BL (Bc*Lc)

// Scratch (device globals; no allocation allowed)
__device__ float g_Q[Bc*Hc*Lc*HDc];
__device__ float g_K[Bc*Hc*Lc*HDc];
__device__ float g_V[Bc*Hc*Lc*HDc];
__device__ float g_ctx[Bc*Lc*Dc];

// ---------------------------------------------------------------------------
// GEMM: out = X @ W^T + bias.  X:[M,K] row-major, W:[N,K] row-major.
// LAYOUT 0: out[r*N+c]  (plain [M,N])
// LAYOUT 1: out in [B,H,L,HD] layout: r=(b*L+l), c=(h*HD+hd)
// Block: 16x16 threads, 64x64 tile, 4x4 microtile, k-step 16.
// ---------------------------------------------------------------------------
template<int LAYOUT>
__global__ void gemm_bias_kernel(const float* __restrict__ X,
                                 const float* __restrict__ W,
                                 const float* __restrict__ bias,
                                 float* __restrict__ out,
                                 int M, int N, int K) {
    __shared__ float As[64][17];
    __shared__ float Bs[64][17];
    const int tx = threadIdx.x, ty = threadIdx.y;
    const int t  = ty * 16 + tx;
    const int row0 = blockIdx.y * 64;
    const int col0 = blockIdx.x * 64;

    float acc[4][4];
#pragma unroll
    for (int i = 0; i < 4; i++)
#pragma unroll
        for (int j = 0; j < 4; j++) acc[i][j] = 0.f;

    for (int k0 = 0; k0 < K; k0 += 16) {
#pragma unroll
        for (int e = 0; e < 4; e++) {
            int lin = e * 256 + t;
            int r = lin >> 4, c = lin & 15;
            As[r][c] = X[(size_t)(row0 + r) * K + k0 + c];
            Bs[r][c] = W[(size_t)(col0 + r) * K + k0 + c];
        }
        __syncthreads();
#pragma unroll
        for (int kk = 0; kk < 16; kk++) {
            float a[4], bv[4];
#pragma unroll
            for (int i = 0; i < 4; i++) a[i] = As[ty * 4 + i][kk];
#pragma unroll
            for (int j = 0; j < 4; j++) bv[j] = Bs[tx * 4 + j][kk];
#pragma unroll
            for (int i = 0; i < 4; i++)
#pragma unroll
                for (int j = 0; j < 4; j++) acc[i][j] += a[i] * bv[j];
        }
        __syncthreads();
    }

#pragma unroll
    for (int i = 0; i < 4; i++) {
        int r = row0 + ty * 4 + i;
#pragma unroll
        for (int j = 0; j < 4; j++) {
            int c = col0 + tx * 4 + j;
            float v = acc[i][j] + bias[c];
            if (LAYOUT == 0) {
                out[(size_t)r * N + c] = v;
            } else {
                int b = r / Lc, lrow = r % Lc;
                int hh = c / HDc, hd = c % HDc;
                out[(((size_t)(b * Hc + hh)) * Lc + lrow) * HDc + hd] = v;
            }
        }
    }
}

// ---------------------------------------------------------------------------
// Causal flash attention.
// Grid: (L/64, H, B).  Block: 256 threads.
// Thread t: query row qi = t/4 within tile; key quarter sub = t%4 (16 keys).
// Partial O accumulated in registers (all 64 dims), quad-reduced via shfl at end.
// Smem: Qs/Ks/Vs 64x65 floats each (dynamic, 49920 B).
// ---------------------------------------------------------------------------
__global__ __launch_bounds__(256, 2)
void flash_attn_kernel(float* __restrict__ ctx) {
    extern __shared__ float sm[];
    float* Qs = sm;               // 64*65
    float* Ks = sm + 64 * 65;     // 64*65
    float* Vs = sm + 2 * 64 * 65; // 64*65

    const int t   = threadIdx.x;
    const int qi  = t >> 2;
    const int sub = t & 3;
    const int qt  = blockIdx.x;
    const int h   = blockIdx.y;
    const int b   = blockIdx.z;
    const size_t base = ((size_t)(b * Hc + h)) * Lc * HDc;

    // Load Q tile
    for (int i = 0; i < 16; i++) {
        int lin = i * 256 + t;
        int r = lin >> 6, c = lin & 63;
        Qs[r * 65 + c] = g_Q[base + (size_t)(qt * 64 + r) * HDc + c];
    }

    float acc[64];
#pragma unroll
    for (int i = 0; i < 64; i++) acc[i] = 0.f;
    float m = -1e30f, l = 0.f;
    const float scale = 0.125f;  // 1/sqrt(64)
    const int qg = qt * 64 + qi;

    for (int jt = 0; jt <= qt; jt++) {
        __syncthreads();  // protect K/V smem (also orders Q load on iter 0)
        for (int i = 0; i < 16; i++) {
            int lin = i * 256 + t;
            int r = lin >> 6, c = lin & 63;
            Ks[r * 65 + c] = g_K[base + (size_t)(jt * 64 + r) * HDc + c];
            Vs[r * 65 + c] = g_V[base + (size_t)(jt * 64 + r) * HDc + c];
        }
        __syncthreads();

        // S = Q K^T for this thread's 16 keys
        float s[16];
#pragma unroll
        for (int j = 0; j < 16; j++) s[j] = 0.f;
        for (int d0 = 0; d0 < 64; d0 += 8) {
            float qreg[8];
#pragma unroll
            for (int d = 0; d < 8; d++) qreg[d] = Qs[qi * 65 + d0 + d];
#pragma unroll
            for (int j = 0; j < 16; j++) {
                const float* kr = &Ks[(sub * 16 + j) * 65 + d0];
#pragma unroll
                for (int d = 0; d < 8; d++) s[j] += qreg[d] * kr[d];
            }
        }
        // scale + causal mask
#pragma unroll
        for (int j = 0; j < 16; j++) {
            int kg = jt * 64 + sub * 16 + j;
            s[j] = (kg <= qg) ? s[j] * scale : -1e30f;
        }
        // row max across quad
        float mloc = s[0];
#pragma unroll
        for (int j = 1; j < 16; j++) mloc = fmaxf(mloc, s[j]);
        mloc = fmaxf(mloc, __shfl_xor_sync(0xffffffffu, mloc, 1));
        mloc = fmaxf(mloc, __shfl_xor_sync(0xffffffffu, mloc, 2));
        float mnew = fmaxf(m, mloc);
        float corr = __expf(m - mnew);
        m = mnew;
        l *= corr;
        float p[16];
#pragma unroll
        for (int j = 0; j < 16; j++) { p[j] = __expf(s[j] - mnew); l += p[j]; }
#pragma unroll
        for (int i = 0; i < 64; i++) acc[i] *= corr;
        // O += P V (thread's 16 keys, all 64 dims)
#pragma unroll
        for (int j = 0; j < 16; j++) {
            const float* vr = &Vs[(sub * 16 + j) * 65];
            float pj = p[j];
#pragma unroll
            for (int dd = 0; dd < 64; dd++) acc[dd] += pj * vr[dd];
        }
    }

    // quad reduce l and O, write ctx in [B,L,D] layout
    l += __shfl_xor_sync(0xffffffffu, l, 1);
    l += __shfl_xor_sync(0xffffffffu, l, 2);
    float inv = 1.f / l;
    float* outp = ctx + ((size_t)b * Lc + qg) * Dc + h * HDc;
#pragma unroll
    for (int dd = 0; dd < 64; dd++) {
        float o = acc[dd];
        o += __shfl_xor_sync(0xffffffffu, o, 1);
        o += __shfl_xor_sync(0xffffffffu, o, 2);
        if ((dd >> 4) == sub) outp[dd] = o * inv;
    }
}

// ---------------------------------------------------------------------------
extern "C" void kernel_launch(void* const* d_in, const int* in_sizes, int n_in,
                              void* d_out, int out_size) {
    const float* q  = (const float*)d_in[0];
    const float* k  = (const float*)d_in[1];
    const float* v  = (const float*)d_in[2];
    // d_in[3] = mask (causal tril; applied analytically)
    const float* Wq = (const float*)d_in[4];
    const float* bq = (const float*)d_in[5];
    const float* Wk = (const float*)d_in[6];
    const float* bk = (const float*)d_in[7];
    const float* Wv = (const float*)d_in[8];
    const float* bv = (const float*)d_in[9];
    const float* Wo = (const float*)d_in[10];
    const float* bo = (const float*)d_in[11];
    float* out = (float*)d_out;

    float *Qp, *Kp, *Vp, *ctx;
    cudaGetSymbolAddress((void**)&Qp, g_Q);
    cudaGetSymbolAddress((void**)&Kp, g_K);
    cudaGetSymbolAddress((void**)&Vp, g_V);
    cudaGetSymbolAddress((void**)&ctx, g_ctx);

    dim3 blk(16, 16);
    dim3 grd_proj(Dc / 64, BL / 64);   // 8 x 128

    gemm_bias_kernel<1><<<grd_proj, blk>>>(q, Wq, bq, Qp, BL, Dc, Dc);
    gemm_bias_kernel<1><<<grd_proj, blk>>>(k, Wk, bk, Kp, BL, Dc, Dc);
    gemm_bias_kernel<1><<<grd_proj, blk>>>(v, Wv, bv, Vp, BL, Dc, Dc);

    const int smem = 3 * 64 * 65 * sizeof(float);  // 49920 B
    cudaFuncSetAttribute(flash_attn_kernel,
                         cudaFuncAttributeMaxDynamicSharedMemorySize, smem);
    dim3 grd_fa(Lc / 64, Hc, Bc);      // 32 x 8 x 4
    flash_attn_kernel<<<grd_fa, 256, smem>>>(ctx);

    gemm_bias_kernel<0><<<grd_proj, blk>>>(ctx, Wo, bo, out, BL, Dc, Dc);
}

// round 5
// speedup vs baseline: 6.4236x; 6.4236x over previous
#include <cuda_runtime.h>
#include <cuda_bf16.h>
#include <math.h>
#include <stdint.h>

#define Bc 4
#define Lc 2048
#define Dc 512
#define Hc 8
#define HDc 64
#define BL (Bc*Lc)

// ---------------- scratch (device globals; no allocation allowed) ----------
__device__ __nv_bfloat16 g_Qh[Bc*Hc*Lc*HDc];
__device__ __nv_bfloat16 g_Ql[Bc*Hc*Lc*HDc];
__device__ __nv_bfloat16 g_Kh[Bc*Hc*Lc*HDc];
__device__ __nv_bfloat16 g_Kl[Bc*Hc*Lc*HDc];
__device__ __nv_bfloat16 g_Vh[Bc*Hc*Lc*HDc];
__device__ __nv_bfloat16 g_Vl[Bc*Hc*Lc*HDc];
__device__ float g_ctx[Bc*Lc*Dc];
__device__ __nv_bfloat16 g_Xhi[BL*Dc];
__device__ __nv_bfloat16 g_Xlo[BL*Dc];
__device__ __nv_bfloat16 g_Whi[Dc*Dc];
__device__ __nv_bfloat16 g_Wlo[Dc*Dc];

// ---------------- helpers ---------------------------------------------------
__device__ __forceinline__ uint32_t smem_u32(const void* p) {
    uint32_t a;
    asm("{ .reg .u64 t; cvta.to.shared.u64 t, %1; cvt.u32.u64 %0, t; }"
        : "=r"(a) : "l"(p));
    return a;
}
__device__ __forceinline__ void ldsm4(uint32_t* r, uint32_t addr) {
    asm volatile("ldmatrix.sync.aligned.m8n8.x4.shared.b16 {%0,%1,%2,%3}, [%4];"
                 : "=r"(r[0]), "=r"(r[1]), "=r"(r[2]), "=r"(r[3]) : "r"(addr));
}
__device__ __forceinline__ void ldsm4t(uint32_t* r, uint32_t addr) {
    asm volatile("ldmatrix.sync.aligned.m8n8.x4.trans.shared.b16 {%0,%1,%2,%3}, [%4];"
                 : "=r"(r[0]), "=r"(r[1]), "=r"(r[2]), "=r"(r[3]) : "r"(addr));
}
__device__ __forceinline__ void mma16816(float* d, const uint32_t* a,
                                         uint32_t b0, uint32_t b1) {
    asm volatile("mma.sync.aligned.m16n8k16.row.col.f32.bf16.bf16.f32 "
                 "{%0,%1,%2,%3}, {%4,%5,%6,%7}, {%8,%9}, {%0,%1,%2,%3};"
                 : "+f"(d[0]), "+f"(d[1]), "+f"(d[2]), "+f"(d[3])
                 : "r"(a[0]), "r"(a[1]), "r"(a[2]), "r"(a[3]), "r"(b0), "r"(b1));
}
__device__ __forceinline__ uint32_t packbf2(float lo, float hi) {
    __nv_bfloat162 v = __floats2bfloat162_rn(lo, hi);
    return *(uint32_t*)&v;
}

// ---------------------------------------------------------------------------
// fp32 -> (bf16 hi, bf16 lo) split conversion
// ---------------------------------------------------------------------------
__global__ void cvt_hilo(const float4* __restrict__ x,
                         __nv_bfloat162* __restrict__ hi,
                         __nv_bfloat162* __restrict__ lo, int n4) {
    int i = blockIdx.x * blockDim.x + threadIdx.x;
    if (i < n4) {
        float4 v = x[i];
        __nv_bfloat16 h0 = __float2bfloat16(v.x);
        __nv_bfloat16 h1 = __float2bfloat16(v.y);
        __nv_bfloat16 h2 = __float2bfloat16(v.z);
        __nv_bfloat16 h3 = __float2bfloat16(v.w);
        hi[2 * i]     = __halves2bfloat162(h0, h1);
        hi[2 * i + 1] = __halves2bfloat162(h2, h3);
        lo[2 * i]     = __halves2bfloat162(__float2bfloat16(v.x - __bfloat162float(h0)),
                                           __float2bfloat16(v.y - __bfloat162float(h1)));
        lo[2 * i + 1] = __halves2bfloat162(__float2bfloat16(v.z - __bfloat162float(h2)),
                                           __float2bfloat16(v.w - __bfloat162float(h3)));
    }
}

// ---------------------------------------------------------------------------
// Warp-MMA GEMM: out = A @ B^T + bias.  A:[8192,512] hi/lo bf16, B:[512,512].
// fp32 accuracy via 3 passes (AhBh + AlBh + AhBl). Block 256 thr (8 warps),
// tile 128x64, warp 32x32, BK=64. Register-prefetch pipeline.
// LAYOUT 0: fp32 out[r*512+c]; LAYOUT 1: bf16 hi/lo out in [B,H,L,HD].
// ---------------------------------------------------------------------------
#define GSTR 144  // smem row stride bytes (64 bf16 = 128B + 16 pad)
template<int LAYOUT>
__global__ void __launch_bounds__(256) gemm_mma(
    const __nv_bfloat16* __restrict__ Ah, const __nv_bfloat16* __restrict__ Al,
    const __nv_bfloat16* __restrict__ Bh, const __nv_bfloat16* __restrict__ Bl,
    const float* __restrict__ bias, float* __restrict__ out,
    __nv_bfloat16* __restrict__ outh, __nv_bfloat16* __restrict__ outl) {
    extern __shared__ char smem[];
    const uint32_t sb = smem_u32(smem);
    const int t = threadIdx.x, lane = t & 31, wid = t >> 5;
    const int wm = wid & 3, wn = wid >> 2;
    const int row0 = blockIdx.y * 128, col0 = blockIdx.x * 64;
    const uint32_t SAH = 0, SAL = 18432, SBH = 36864, SBL = 46080;

    float d[2][4][4];
#pragma unroll
    for (int i = 0; i < 2; i++)
#pragma unroll
        for (int j = 0; j < 4; j++)
#pragma unroll
            for (int e = 0; e < 4; e++) d[i][j][e] = 0.f;

    uint4 ra_h[4], ra_l[4], rb_h[2], rb_l[2];

    auto gload = [&](int kc) {
        const int k0 = kc * 64;
#pragma unroll
        for (int i = 0; i < 4; i++) {
            int idx = i * 256 + t, r = idx >> 3, ce = (idx & 7) * 8;
            size_t g = (size_t)(row0 + r) * 512 + k0 + ce;
            ra_h[i] = *(const uint4*)(Ah + g);
            ra_l[i] = *(const uint4*)(Al + g);
        }
#pragma unroll
        for (int i = 0; i < 2; i++) {
            int idx = i * 256 + t, r = idx >> 3, ce = (idx & 7) * 8;
            size_t g = (size_t)(col0 + r) * 512 + k0 + ce;
            rb_h[i] = *(const uint4*)(Bh + g);
            rb_l[i] = *(const uint4*)(Bl + g);
        }
    };
    auto sstore = [&]() {
#pragma unroll
        for (int i = 0; i < 4; i++) {
            int idx = i * 256 + t, r = idx >> 3, cb = (idx & 7) * 16;
            *(uint4*)(smem + SAH + r * GSTR + cb) = ra_h[i];
            *(uint4*)(smem + SAL + r * GSTR + cb) = ra_l[i];
        }
#pragma unroll
        for (int i = 0; i < 2; i++) {
            int idx = i * 256 + t, r = idx >> 3, cb = (idx & 7) * 16;
            *(uint4*)(smem + SBH + r * GSTR + cb) = rb_h[i];
            *(uint4*)(smem + SBL + r * GSTR + cb) = rb_l[i];
        }
    };

    gload(0);
    for (int c = 0; c < 8; c++) {
        __syncthreads();
        sstore();
        __syncthreads();
        if (c < 7) gload(c + 1);
#pragma unroll
        for (int pass = 0; pass < 3; pass++) {
            uint32_t abase = sb + (pass == 1 ? SAL : SAH);
            uint32_t bbase = sb + (pass == 2 ? SBL : SBH);
#pragma unroll
            for (int ks = 0; ks < 4; ks++) {
                uint32_t af[2][4], bf[2][4];
#pragma unroll
                for (int mt = 0; mt < 2; mt++)
                    ldsm4(af[mt], abase + (wm * 32 + mt * 16 + (lane & 15)) * GSTR
                                  + ks * 32 + (lane >> 4) * 16);
#pragma unroll
                for (int bp = 0; bp < 2; bp++)
                    ldsm4(bf[bp], bbase + (wn * 32 + bp * 16 + (lane & 15)) * GSTR
                                  + ks * 32 + (lane >> 4) * 16);
#pragma unroll
                for (int mt = 0; mt < 2; mt++)
#pragma unroll
                    for (int nt = 0; nt < 4; nt++)
                        mma16816(d[mt][nt], af[mt], bf[nt >> 1][nt & 1], bf[nt >> 1][(nt & 1) + 2]);
            }
        }
    }

    // epilogue
#pragma unroll
    for (int mt = 0; mt < 2; mt++) {
        int r1 = row0 + wm * 32 + mt * 16 + (lane >> 2);
#pragma unroll
        for (int nt = 0; nt < 4; nt++) {
            int cc = col0 + wn * 32 + nt * 8 + (lane & 3) * 2;
            float b0 = bias[cc], b1 = bias[cc + 1];
            float v00 = d[mt][nt][0] + b0, v01 = d[mt][nt][1] + b1;
            float v10 = d[mt][nt][2] + b0, v11 = d[mt][nt][3] + b1;
            if (LAYOUT == 0) {
                *(float2*)(out + (size_t)r1 * 512 + cc) = make_float2(v00, v01);
                *(float2*)(out + (size_t)(r1 + 8) * 512 + cc) = make_float2(v10, v11);
            } else {
                int hd = cc - col0;
#pragma unroll
                for (int rr = 0; rr < 2; rr++) {
                    int r = r1 + rr * 8;
                    float va = rr ? v10 : v00, vb2 = rr ? v11 : v01;
                    int b = r >> 11, l = r & 2047;
                    size_t idx = (((size_t)(b * Hc + blockIdx.x)) * Lc + l) * HDc + hd;
                    __nv_bfloat16 ha = __float2bfloat16(va), hb = __float2bfloat16(vb2);
                    *(__nv_bfloat162*)(outh + idx) = __halves2bfloat162(ha, hb);
                    *(__nv_bfloat162*)(outl + idx) = __halves2bfloat162(
                        __float2bfloat16(va - __bfloat162float(ha)),
                        __float2bfloat16(vb2 - __bfloat162float(hb)));
                }
            }
        }
    }
}

// ---------------------------------------------------------------------------
// Warp-MMA causal flash attention. Grid (32, H, B), block 128 (4 warps).
// Warp w owns query rows w*16..w*16+15 of a 64-query tile.
// S = QK^T: 3 hi/lo passes; softmax fp32 in fragments; PV: 3 hi/lo passes.
// ---------------------------------------------------------------------------
__global__ void __launch_bounds__(128) flash_mma(float* __restrict__ ctx) {
    extern __shared__ char smem[];
    const uint32_t sb = smem_u32(smem);
    const int t = threadIdx.x, lane = t & 31, w = t >> 5;
    const int qt = 31 - blockIdx.x;  // heavy tiles first
    const int h = blockIdx.y, b = blockIdx.z;
    const size_t base = ((size_t)(b * Hc + h)) * Lc * HDc;
    const uint32_t SQH = 0, SQL = 9216, SKH = 18432, SKL = 27648, SVH = 36864, SVL = 46080;

    // load Q tile (64 rows x 64 bf16, hi+lo)
#pragma unroll
    for (int i = 0; i < 4; i++) {
        int idx = i * 128 + t, r = idx >> 3, cb = (idx & 7) * 16, ce = (idx & 7) * 8;
        size_t g = base + (size_t)(qt * 64 + r) * HDc + ce;
        *(uint4*)(smem + SQH + r * GSTR + cb) = *(const uint4*)(g_Qh + g);
        *(uint4*)(smem + SQL + r * GSTR + cb) = *(const uint4*)(g_Ql + g);
    }
    __syncthreads();

    uint32_t qfh[4][4], qfl[4][4];
#pragma unroll
    for (int ks = 0; ks < 4; ks++) {
        uint32_t a = (w * 16 + (lane & 15)) * GSTR + ks * 32 + (lane >> 4) * 16;
        ldsm4(qfh[ks], sb + SQH + a);
        ldsm4(qfl[ks], sb + SQL + a);
    }

    float o[8][4];
#pragma unroll
    for (int i = 0; i < 8; i++)
#pragma unroll
        for (int e = 0; e < 4; e++) o[i][e] = 0.f;
    float m0 = -1e30f, m1 = -1e30f, l0 = 0.f, l1 = 0.f;
    const float scale = 0.125f;

    for (int jt = 0; jt <= qt; jt++) {
        __syncthreads();
#pragma unroll
        for (int i = 0; i < 4; i++) {
            int idx = i * 128 + t, r = idx >> 3, cb = (idx & 7) * 16, ce = (idx & 7) * 8;
            size_t g = base + (size_t)(jt * 64 + r) * HDc + ce;
            *(uint4*)(smem + SKH + r * GSTR + cb) = *(const uint4*)(g_Kh + g);
            *(uint4*)(smem + SKL + r * GSTR + cb) = *(const uint4*)(g_Kl + g);
            *(uint4*)(smem + SVH + r * GSTR + cb) = *(const uint4*)(g_Vh + g);
            *(uint4*)(smem + SVL + r * GSTR + cb) = *(const uint4*)(g_Vl + g);
        }
        __syncthreads();

        // ---- S = Q K^T (3 passes) ----
        float s[8][4];
#pragma unroll
        for (int i = 0; i < 8; i++)
#pragma unroll
            for (int e = 0; e < 4; e++) s[i][e] = 0.f;
#pragma unroll
        for (int pass = 0; pass < 3; pass++) {
            const uint32_t (*af)[4] = (pass == 1) ? qfl : qfh;
            uint32_t bbase = sb + ((pass == 2) ? SKL : SKH);
#pragma unroll
            for (int ks = 0; ks < 4; ks++) {
#pragma unroll
                for (int bp = 0; bp < 4; bp++) {
                    uint32_t bf[4];
                    ldsm4(bf, bbase + (bp * 16 + (lane & 15)) * GSTR + ks * 32 + (lane >> 4) * 16);
                    mma16816(s[bp * 2],     af[ks], bf[0], bf[2]);
                    mma16816(s[bp * 2 + 1], af[ks], bf[1], bf[3]);
                }
            }
        }

        // ---- scale + causal mask ----
        if (jt == qt) {
            int q0 = w * 16 + (lane >> 2);
#pragma unroll
            for (int nt = 0; nt < 8; nt++) {
                int kc = nt * 8 + (lane & 3) * 2;
                s[nt][0] = (kc     <= q0)     ? s[nt][0] * scale : -1e30f;
                s[nt][1] = (kc + 1 <= q0)     ? s[nt][1] * scale : -1e30f;
                s[nt][2] = (kc     <= q0 + 8) ? s[nt][2] * scale : -1e30f;
                s[nt][3] = (kc + 1 <= q0 + 8) ? s[nt][3] * scale : -1e30f;
            }
        } else {
#pragma unroll
            for (int nt = 0; nt < 8; nt++)
#pragma unroll
                for (int e = 0; e < 4; e++) s[nt][e] *= scale;
        }

        // ---- online softmax ----
        float a0 = -1e30f, a1 = -1e30f;
#pragma unroll
        for (int nt = 0; nt < 8; nt++) {
            a0 = fmaxf(a0, fmaxf(s[nt][0], s[nt][1]));
            a1 = fmaxf(a1, fmaxf(s[nt][2], s[nt][3]));
        }
        a0 = fmaxf(a0, __shfl_xor_sync(0xffffffffu, a0, 1));
        a0 = fmaxf(a0, __shfl_xor_sync(0xffffffffu, a0, 2));
        a1 = fmaxf(a1, __shfl_xor_sync(0xffffffffu, a1, 1));
        a1 = fmaxf(a1, __shfl_xor_sync(0xffffffffu, a1, 2));
        float n0 = fmaxf(m0, a0), n1 = fmaxf(m1, a1);
        float c0 = __expf(m0 - n0), c1 = __expf(m1 - n1);
        m0 = n0; m1 = n1; l0 *= c0; l1 *= c1;
#pragma unroll
        for (int nt = 0; nt < 8; nt++) {
            o[nt][0] *= c0; o[nt][1] *= c0; o[nt][2] *= c1; o[nt][3] *= c1;
        }

        // ---- P = exp(S - m); PV accumulation, per k-step ----
#pragma unroll
        for (int ks = 0; ks < 4; ks++) {
            float p[8];
            p[0] = __expf(s[2 * ks][0] - n0);     p[1] = __expf(s[2 * ks][1] - n0);
            p[2] = __expf(s[2 * ks][2] - n1);     p[3] = __expf(s[2 * ks][3] - n1);
            p[4] = __expf(s[2 * ks + 1][0] - n0); p[5] = __expf(s[2 * ks + 1][1] - n0);
            p[6] = __expf(s[2 * ks + 1][2] - n1); p[7] = __expf(s[2 * ks + 1][3] - n1);
            l0 += p[0] + p[1] + p[4] + p[5];
            l1 += p[2] + p[3] + p[6] + p[7];
            uint32_t ph[4], pl[4];
#pragma unroll
            for (int j = 0; j < 4; j++) {
                float e0 = p[j * 2], e1 = p[j * 2 + 1];
                ph[j] = packbf2(e0, e1);
                __nv_bfloat162 hv = *(__nv_bfloat162*)&ph[j];
                pl[j] = packbf2(e0 - __bfloat162float(hv.x), e1 - __bfloat162float(hv.y));
            }
            // A-frag order: {tile2ks.c01, tile2ks.c23, tile2ks+1.c01, tile2ks+1.c23}
            uint32_t pA_h[4] = { ph[0], ph[1], ph[2], ph[3] };
            uint32_t pA_l[4] = { pl[0], pl[1], pl[2], pl[3] };
#pragma unroll
            for (int np = 0; np < 4; np++) {
                uint32_t a = (ks * 16 + (lane & 15)) * GSTR + np * 32 + (lane >> 4) * 16;
                uint32_t vh[4], vl[4];
                ldsm4t(vh, sb + SVH + a);
                ldsm4t(vl, sb + SVL + a);
                mma16816(o[np * 2],     pA_h, vh[0], vh[1]);
                mma16816(o[np * 2 + 1], pA_h, vh[2], vh[3]);
                mma16816(o[np * 2],     pA_l, vh[0], vh[1]);
                mma16816(o[np * 2 + 1], pA_l, vh[2], vh[3]);
                mma16816(o[np * 2],     pA_h, vl[0], vl[1]);
                mma16816(o[np * 2 + 1], pA_h, vl[2], vl[3]);
            }
        }
    }

    // ---- finalize ----
    l0 += __shfl_xor_sync(0xffffffffu, l0, 1);
    l0 += __shfl_xor_sync(0xffffffffu, l0, 2);
    l1 += __shfl_xor_sync(0xffffffffu, l1, 1);
    l1 += __shfl_xor_sync(0xffffffffu, l1, 2);
    float i0 = 1.f / l0, i1 = 1.f / l1;
    int qrow = qt * 64 + w * 16 + (lane >> 2);
    float* op = ctx + ((size_t)b * Lc + qrow) * Dc + h * HDc;
#pragma unroll
    for (int nt = 0; nt < 8; nt++) {
        int cc = nt * 8 + (lane & 3) * 2;
        *(float2*)(op + cc) = make_float2(o[nt][0] * i0, o[nt][1] * i0);
        *(float2*)(op + 8 * Dc + cc) = make_float2(o[nt][2] * i1, o[nt][3] * i1);
    }
}

// ---------------------------------------------------------------------------
extern "C" void kernel_launch(void* const* d_in, const int* in_sizes, int n_in,
                              void* d_out, int out_size) {
    const float* q  = (const float*)d_in[0];
    const float* k  = (const float*)d_in[1];
    const float* v  = (const float*)d_in[2];
    const float* Wq = (const float*)d_in[4];
    const float* bq = (const float*)d_in[5];
    const float* Wk = (const float*)d_in[6];
    const float* bk = (const float*)d_in[7];
    const float* Wv = (const float*)d_in[8];
    const float* bv = (const float*)d_in[9];
    const float* Wo = (const float*)d_in[10];
    const float* bo = (const float*)d_in[11];
    float* out = (float*)d_out;

    __nv_bfloat16 *Qh, *Ql, *Kh, *Kl, *Vh, *Vl, *Xhi, *Xlo, *Whi, *Wlo;
    float* ctx;
    cudaGetSymbolAddress((void**)&Qh, g_Qh);
    cudaGetSymbolAddress((void**)&Ql, g_Ql);
    cudaGetSymbolAddress((void**)&Kh, g_Kh);
    cudaGetSymbolAddress((void**)&Kl, g_Kl);
    cudaGetSymbolAddress((void**)&Vh, g_Vh);
    cudaGetSymbolAddress((void**)&Vl, g_Vl);
    cudaGetSymbolAddress((void**)&ctx, g_ctx);
    cudaGetSymbolAddress((void**)&Xhi, g_Xhi);
    cudaGetSymbolAddress((void**)&Xlo, g_Xlo);
    cudaGetSymbolAddress((void**)&Whi, g_Whi);
    cudaGetSymbolAddress((void**)&Wlo, g_Wlo);

    const int smem_sz = 55296;
    cudaFuncSetAttribute(gemm_mma<0>, cudaFuncAttributeMaxDynamicSharedMemorySize, smem_sz);
    cudaFuncSetAttribute(gemm_mma<1>, cudaFuncAttributeMaxDynamicSharedMemorySize, smem_sz);
    cudaFuncSetAttribute(flash_mma, cudaFuncAttributeMaxDynamicSharedMemorySize, smem_sz);

    const int nX4 = BL * Dc / 4, nW4 = Dc * Dc / 4;
    dim3 grd_gemm(Dc / 64, BL / 128);  // 8 x 64

    cvt_hilo<<<(nX4 + 255) / 256, 256>>>((const float4*)q, (__nv_bfloat162*)Xhi, (__nv_bfloat162*)Xlo, nX4);
    cvt_hilo<<<(nW4 + 255) / 256, 256>>>((const float4*)Wq, (__nv_bfloat162*)Whi, (__nv_bfloat162*)Wlo, nW4);
    gemm_mma<1><<<grd_gemm, 256, smem_sz>>>(Xhi, Xlo, Whi, Wlo, bq, nullptr, Qh, Ql);

    cvt_hilo<<<(nX4 + 255) / 256, 256>>>((const float4*)k, (__nv_bfloat162*)Xhi, (__nv_bfloat162*)Xlo, nX4);
    cvt_hilo<<<(nW4 + 255) / 256, 256>>>((const float4*)Wk, (__nv_bfloat162*)Whi, (__nv_bfloat162*)Wlo, nW4);
    gemm_mma<1><<<grd_gemm, 256, smem_sz>>>(Xhi, Xlo, Whi, Wlo, bk, nullptr, Kh, Kl);

    cvt_hilo<<<(nX4 + 255) / 256, 256>>>((const float4*)v, (__nv_bfloat162*)Xhi, (__nv_bfloat162*)Xlo, nX4);
    cvt_hilo<<<(nW4 + 255) / 256, 256>>>((const float4*)Wv, (__nv_bfloat162*)Whi, (__nv_bfloat162*)Wlo, nW4);
    gemm_mma<1><<<grd_gemm, 256, smem_sz>>>(Xhi, Xlo, Whi, Wlo, bv, nullptr, Vh, Vl);

    dim3 grd_fa(Lc / 64, Hc, Bc);
    flash_mma<<<grd_fa, 128, smem_sz>>>(ctx);

    cvt_hilo<<<(nX4 + 255) / 256, 256>>>((const float4*)ctx, (__nv_bfloat162*)Xhi, (__nv_bfloat162*)Xlo, nX4);
    cvt_hilo<<<(nW4 + 255) / 256, 256>>>((const float4*)Wo, (__nv_bfloat162*)Whi, (__nv_bfloat162*)Wlo, nW4);
    gemm_mma<0><<<grd_gemm, 256, smem_sz>>>(Xhi, Xlo, Whi, Wlo, bo, out, nullptr, nullptr);
}

// round 6
// speedup vs baseline: 6.7623x; 1.0527x over previous
#include <cuda_runtime.h>
#include <cuda_bf16.h>
#include <math.h>
#include <stdint.h>

#define Bc 4
#define Lc 2048
#define Dc 512
#define Hc 8
#define HDc 64
#define BL (Bc*Lc)

// ---------------- scratch (device globals; no allocation allowed) ----------
__device__ __nv_bfloat16 g_Qh[Bc*Hc*Lc*HDc];
__device__ __nv_bfloat16 g_Ql[Bc*Hc*Lc*HDc];
__device__ __nv_bfloat16 g_Kh[Bc*Hc*Lc*HDc];
__device__ __nv_bfloat16 g_Kl[Bc*Hc*Lc*HDc];
__device__ __nv_bfloat16 g_Vh[Bc*Hc*Lc*HDc];
__device__ __nv_bfloat16 g_Vl[Bc*Hc*Lc*HDc];
__device__ __nv_bfloat16 g_CXh[BL*Dc];
__device__ __nv_bfloat16 g_CXl[BL*Dc];

// ---------------- helpers ---------------------------------------------------
__device__ __forceinline__ uint32_t smem_u32(const void* p) {
    uint32_t a;
    asm("{ .reg .u64 t; cvta.to.shared.u64 t, %1; cvt.u32.u64 %0, t; }"
        : "=r"(a) : "l"(p));
    return a;
}
__device__ __forceinline__ void ldsm4(uint32_t* r, uint32_t addr) {
    asm volatile("ldmatrix.sync.aligned.m8n8.x4.shared.b16 {%0,%1,%2,%3}, [%4];"
                 : "=r"(r[0]), "=r"(r[1]), "=r"(r[2]), "=r"(r[3]) : "r"(addr));
}
__device__ __forceinline__ void ldsm4t(uint32_t* r, uint32_t addr) {
    asm volatile("ldmatrix.sync.aligned.m8n8.x4.trans.shared.b16 {%0,%1,%2,%3}, [%4];"
                 : "=r"(r[0]), "=r"(r[1]), "=r"(r[2]), "=r"(r[3]) : "r"(addr));
}
__device__ __forceinline__ void mma16816(float* d, const uint32_t* a,
                                         uint32_t b0, uint32_t b1) {
    asm volatile("mma.sync.aligned.m16n8k16.row.col.f32.bf16.bf16.f32 "
                 "{%0,%1,%2,%3}, {%4,%5,%6,%7}, {%8,%9}, {%0,%1,%2,%3};"
                 : "+f"(d[0]), "+f"(d[1]), "+f"(d[2]), "+f"(d[3])
                 : "r"(a[0]), "r"(a[1]), "r"(a[2]), "r"(a[3]), "r"(b0), "r"(b1));
}
__device__ __forceinline__ uint32_t packbf2(float lo, float hi) {
    __nv_bfloat162 v = __floats2bfloat162_rn(lo, hi);
    return *(uint32_t*)&v;
}
// convert 8 fp32 (two float4) -> hi uint4 + lo uint4 (bf16x2 lanes)
__device__ __forceinline__ void split8(const float4 v0, const float4 v1,
                                       uint4& hi, uint4& lo) {
    hi.x = packbf2(v0.x, v0.y); hi.y = packbf2(v0.z, v0.w);
    hi.z = packbf2(v1.x, v1.y); hi.w = packbf2(v1.z, v1.w);
    __nv_bfloat162 h;
    h = *(__nv_bfloat162*)&hi.x;
    lo.x = packbf2(v0.x - __bfloat162float(h.x), v0.y - __bfloat162float(h.y));
    h = *(__nv_bfloat162*)&hi.y;
    lo.y = packbf2(v0.z - __bfloat162float(h.x), v0.w - __bfloat162float(h.y));
    h = *(__nv_bfloat162*)&hi.z;
    lo.z = packbf2(v1.x - __bfloat162float(h.x), v1.y - __bfloat162float(h.y));
    h = *(__nv_bfloat162*)&hi.w;
    lo.w = packbf2(v1.z - __bfloat162float(h.x), v1.w - __bfloat162float(h.y));
}

// ---------------------------------------------------------------------------
// Warp-MMA GEMM: out = A @ W^T + bias, fp32 accuracy via 3 hi/lo passes.
// MODE 1 (projection): A fp32 [8192,512], out = bf16 hi/lo in [B,H,L,HD].
// MODE 0 (output proj): A bf16 hi/lo [8192,512], out fp32 [8192,512].
// W always fp32 [512,512]; converted in the loader.
// Block 256 thr (8 warps), tile 128x64, warp 32x32, BK=64.
// ---------------------------------------------------------------------------
#define GSTR 144  // smem row stride bytes (64 bf16 = 128B + 16 pad)
template<int MODE>
__global__ void __launch_bounds__(256) gemm_mma(
    const float* __restrict__ Afp,
    const __nv_bfloat16* __restrict__ Ah, const __nv_bfloat16* __restrict__ Al,
    const float* __restrict__ W,
    const float* __restrict__ bias, float* __restrict__ out,
    __nv_bfloat16* __restrict__ outh, __nv_bfloat16* __restrict__ outl) {
    extern __shared__ char smem[];
    const uint32_t sb = smem_u32(smem);
    const int t = threadIdx.x, lane = t & 31, wid = t >> 5;
    const int wm = wid & 3, wn = wid >> 2;
    const int row0 = blockIdx.y * 128, col0 = blockIdx.x * 64;
    const uint32_t SAH = 0, SAL = 18432, SBH = 36864, SBL = 46080;

    float d[2][4][4];
#pragma unroll
    for (int i = 0; i < 2; i++)
#pragma unroll
        for (int j = 0; j < 4; j++)
#pragma unroll
            for (int e = 0; e < 4; e++) d[i][j][e] = 0.f;

    // prefetch registers
    float4 va[4][2];             // MODE 1: A fp32
    uint4 ra_h[4], ra_l[4];      // MODE 0: A bf16 hi/lo
    float4 vb[2][2];             // W fp32

    auto gload = [&](int kc) {
        const int k0 = kc * 64;
#pragma unroll
        for (int i = 0; i < 4; i++) {
            int idx = i * 256 + t, r = idx >> 3, ce = (idx & 7) * 8;
            if (MODE == 1) {
                const float4* src = (const float4*)(Afp + (size_t)(row0 + r) * 512 + k0 + ce);
                va[i][0] = src[0]; va[i][1] = src[1];
            } else {
                size_t g = (size_t)(row0 + r) * 512 + k0 + ce;
                ra_h[i] = *(const uint4*)(Ah + g);
                ra_l[i] = *(const uint4*)(Al + g);
            }
        }
#pragma unroll
        for (int i = 0; i < 2; i++) {
            int idx = i * 256 + t, r = idx >> 3, ce = (idx & 7) * 8;
            const float4* src = (const float4*)(W + (size_t)(col0 + r) * 512 + k0 + ce);
            vb[i][0] = src[0]; vb[i][1] = src[1];
        }
    };
    auto sstore = [&]() {
#pragma unroll
        for (int i = 0; i < 4; i++) {
            int idx = i * 256 + t, r = idx >> 3, cb = (idx & 7) * 16;
            uint4 hi, lo;
            if (MODE == 1) split8(va[i][0], va[i][1], hi, lo);
            else { hi = ra_h[i]; lo = ra_l[i]; }
            *(uint4*)(smem + SAH + r * GSTR + cb) = hi;
            *(uint4*)(smem + SAL + r * GSTR + cb) = lo;
        }
#pragma unroll
        for (int i = 0; i < 2; i++) {
            int idx = i * 256 + t, r = idx >> 3, cb = (idx & 7) * 16;
            uint4 hi, lo;
            split8(vb[i][0], vb[i][1], hi, lo);
            *(uint4*)(smem + SBH + r * GSTR + cb) = hi;
            *(uint4*)(smem + SBL + r * GSTR + cb) = lo;
        }
    };

    gload(0);
    for (int c = 0; c < 8; c++) {
        __syncthreads();
        sstore();
        __syncthreads();
        if (c < 7) gload(c + 1);
#pragma unroll
        for (int pass = 0; pass < 3; pass++) {
            uint32_t abase = sb + (pass == 1 ? SAL : SAH);
            uint32_t bbase = sb + (pass == 2 ? SBL : SBH);
#pragma unroll
            for (int ks = 0; ks < 4; ks++) {
                uint32_t af[2][4], bf[2][4];
#pragma unroll
                for (int mt = 0; mt < 2; mt++)
                    ldsm4(af[mt], abase + (wm * 32 + mt * 16 + (lane & 15)) * GSTR
                                  + ks * 32 + (lane >> 4) * 16);
#pragma unroll
                for (int bp = 0; bp < 2; bp++)
                    ldsm4(bf[bp], bbase + (wn * 32 + bp * 16 + (lane & 15)) * GSTR
                                  + ks * 32 + (lane >> 4) * 16);
#pragma unroll
                for (int mt = 0; mt < 2; mt++)
#pragma unroll
                    for (int nt = 0; nt < 4; nt++)
                        mma16816(d[mt][nt], af[mt], bf[nt >> 1][nt & 1], bf[nt >> 1][(nt & 1) + 2]);
            }
        }
    }

    // epilogue
#pragma unroll
    for (int mt = 0; mt < 2; mt++) {
        int r1 = row0 + wm * 32 + mt * 16 + (lane >> 2);
#pragma unroll
        for (int nt = 0; nt < 4; nt++) {
            int cc = col0 + wn * 32 + nt * 8 + (lane & 3) * 2;
            float b0 = bias[cc], b1 = bias[cc + 1];
            float v00 = d[mt][nt][0] + b0, v01 = d[mt][nt][1] + b1;
            float v10 = d[mt][nt][2] + b0, v11 = d[mt][nt][3] + b1;
            if (MODE == 0) {
                *(float2*)(out + (size_t)r1 * 512 + cc) = make_float2(v00, v01);
                *(float2*)(out + (size_t)(r1 + 8) * 512 + cc) = make_float2(v10, v11);
            } else {
                int hd = cc - col0;
#pragma unroll
                for (int rr = 0; rr < 2; rr++) {
                    int r = r1 + rr * 8;
                    float va0 = rr ? v10 : v00, va1 = rr ? v11 : v01;
                    int b = r >> 11, l = r & 2047;
                    size_t idx = (((size_t)(b * Hc + blockIdx.x)) * Lc + l) * HDc + hd;
                    __nv_bfloat16 ha = __float2bfloat16(va0), hb = __float2bfloat16(va1);
                    *(__nv_bfloat162*)(outh + idx) = __halves2bfloat162(ha, hb);
                    *(__nv_bfloat162*)(outl + idx) = __halves2bfloat162(
                        __float2bfloat16(va0 - __bfloat162float(ha)),
                        __float2bfloat16(va1 - __bfloat162float(hb)));
                }
            }
        }
    }
}

// ---------------------------------------------------------------------------
// Warp-MMA causal flash attention. Grid (16, H, B), block 256 (8 warps).
// 128-query tile; warp w owns rows w*16..+15. K/V tiles 64-wide.
// Output written directly as bf16 hi/lo ctx in [B,L,D].
// ---------------------------------------------------------------------------
__global__ void __launch_bounds__(256) flash_mma() {
    extern __shared__ char smem[];
    const uint32_t sb = smem_u32(smem);
    const int t = threadIdx.x, lane = t & 31, w = t >> 5;
    const int qt = 15 - blockIdx.x;  // heavy tiles first
    const int h = blockIdx.y, b = blockIdx.z;
    const size_t base = ((size_t)(b * Hc + h)) * Lc * HDc;
    const uint32_t SQH = 0, SQL = 18432, SKH = 36864, SKL = 46080, SVH = 55296, SVL = 64512;

    // load Q tile (128 rows x 64 bf16, hi+lo)
#pragma unroll
    for (int i = 0; i < 4; i++) {
        int idx = i * 256 + t, r = idx >> 3, cb = (idx & 7) * 16, ce = (idx & 7) * 8;
        size_t g = base + (size_t)(qt * 128 + r) * HDc + ce;
        *(uint4*)(smem + SQH + r * GSTR + cb) = *(const uint4*)(g_Qh + g);
        *(uint4*)(smem + SQL + r * GSTR + cb) = *(const uint4*)(g_Ql + g);
    }
    __syncthreads();

    uint32_t qfh[4][4], qfl[4][4];
#pragma unroll
    for (int ks = 0; ks < 4; ks++) {
        uint32_t a = (w * 16 + (lane & 15)) * GSTR + ks * 32 + (lane >> 4) * 16;
        ldsm4(qfh[ks], sb + SQH + a);
        ldsm4(qfl[ks], sb + SQL + a);
    }

    float o[8][4];
#pragma unroll
    for (int i = 0; i < 8; i++)
#pragma unroll
        for (int e = 0; e < 4; e++) o[i][e] = 0.f;
    float m0 = -1e30f, m1 = -1e30f, l0 = 0.f, l1 = 0.f;
    const float scale = 0.125f;
    const int qlo = qt * 128 + w * 16;
    const int njt = 2 * qt + 2;

    for (int jt = 0; jt < njt; jt++) {
        __syncthreads();
#pragma unroll
        for (int i = 0; i < 2; i++) {
            int idx = i * 256 + t, r = idx >> 3, cb = (idx & 7) * 16, ce = (idx & 7) * 8;
            size_t g = base + (size_t)(jt * 64 + r) * HDc + ce;
            *(uint4*)(smem + SKH + r * GSTR + cb) = *(const uint4*)(g_Kh + g);
            *(uint4*)(smem + SKL + r * GSTR + cb) = *(const uint4*)(g_Kl + g);
            *(uint4*)(smem + SVH + r * GSTR + cb) = *(const uint4*)(g_Vh + g);
            *(uint4*)(smem + SVL + r * GSTR + cb) = *(const uint4*)(g_Vl + g);
        }
        __syncthreads();

        const int J0 = jt * 64;
        if (J0 > qlo + 15) continue;  // fully masked for this warp

        // ---- S = Q K^T (3 passes) ----
        float s[8][4];
#pragma unroll
        for (int i = 0; i < 8; i++)
#pragma unroll
            for (int e = 0; e < 4; e++) s[i][e] = 0.f;
#pragma unroll
        for (int pass = 0; pass < 3; pass++) {
            const uint32_t (*af)[4] = (pass == 1) ? qfl : qfh;
            uint32_t bbase = sb + ((pass == 2) ? SKL : SKH);
#pragma unroll
            for (int ks = 0; ks < 4; ks++) {
#pragma unroll
                for (int bp = 0; bp < 4; bp++) {
                    uint32_t bf[4];
                    ldsm4(bf, bbase + (bp * 16 + (lane & 15)) * GSTR + ks * 32 + (lane >> 4) * 16);
                    mma16816(s[bp * 2],     af[ks], bf[0], bf[2]);
                    mma16816(s[bp * 2 + 1], af[ks], bf[1], bf[3]);
                }
            }
        }

        // ---- scale + causal mask ----
        if (J0 + 63 > qlo) {
            int q0 = qlo + (lane >> 2);
#pragma unroll
            for (int nt = 0; nt < 8; nt++) {
                int kc = J0 + nt * 8 + (lane & 3) * 2;
                s[nt][0] = (kc     <= q0)     ? s[nt][0] * scale : -1e30f;
                s[nt][1] = (kc + 1 <= q0)     ? s[nt][1] * scale : -1e30f;
                s[nt][2] = (kc     <= q0 + 8) ? s[nt][2] * scale : -1e30f;
                s[nt][3] = (kc + 1 <= q0 + 8) ? s[nt][3] * scale : -1e30f;
            }
        } else {
#pragma unroll
            for (int nt = 0; nt < 8; nt++)
#pragma unroll
                for (int e = 0; e < 4; e++) s[nt][e] *= scale;
        }

        // ---- online softmax ----
        float a0 = -1e30f, a1 = -1e30f;
#pragma unroll
        for (int nt = 0; nt < 8; nt++) {
            a0 = fmaxf(a0, fmaxf(s[nt][0], s[nt][1]));
            a1 = fmaxf(a1, fmaxf(s[nt][2], s[nt][3]));
        }
        a0 = fmaxf(a0, __shfl_xor_sync(0xffffffffu, a0, 1));
        a0 = fmaxf(a0, __shfl_xor_sync(0xffffffffu, a0, 2));
        a1 = fmaxf(a1, __shfl_xor_sync(0xffffffffu, a1, 1));
        a1 = fmaxf(a1, __shfl_xor_sync(0xffffffffu, a1, 2));
        float n0 = fmaxf(m0, a0), n1 = fmaxf(m1, a1);
        float c0 = __expf(m0 - n0), c1 = __expf(m1 - n1);
        m0 = n0; m1 = n1; l0 *= c0; l1 *= c1;
#pragma unroll
        for (int nt = 0; nt < 8; nt++) {
            o[nt][0] *= c0; o[nt][1] *= c0; o[nt][2] *= c1; o[nt][3] *= c1;
        }

        // ---- P = exp(S - m); PV accumulation, per k-step ----
#pragma unroll
        for (int ks = 0; ks < 4; ks++) {
            float p[8];
            p[0] = __expf(s[2 * ks][0] - n0);     p[1] = __expf(s[2 * ks][1] - n0);
            p[2] = __expf(s[2 * ks][2] - n1);     p[3] = __expf(s[2 * ks][3] - n1);
            p[4] = __expf(s[2 * ks + 1][0] - n0); p[5] = __expf(s[2 * ks + 1][1] - n0);
            p[6] = __expf(s[2 * ks + 1][2] - n1); p[7] = __expf(s[2 * ks + 1][3] - n1);
            l0 += p[0] + p[1] + p[4] + p[5];
            l1 += p[2] + p[3] + p[6] + p[7];
            uint32_t ph[4], pl[4];
#pragma unroll
            for (int j = 0; j < 4; j++) {
                float e0 = p[j * 2], e1 = p[j * 2 + 1];
                ph[j] = packbf2(e0, e1);
                __nv_bfloat162 hv = *(__nv_bfloat162*)&ph[j];
                pl[j] = packbf2(e0 - __bfloat162float(hv.x), e1 - __bfloat162float(hv.y));
            }
#pragma unroll
            for (int np = 0; np < 4; np++) {
                uint32_t a = (ks * 16 + (lane & 15)) * GSTR + np * 32 + (lane >> 4) * 16;
                uint32_t vh[4], vl[4];
                ldsm4t(vh, sb + SVH + a);
                ldsm4t(vl, sb + SVL + a);
                mma16816(o[np * 2],     ph, vh[0], vh[1]);
                mma16816(o[np * 2 + 1], ph, vh[2], vh[3]);
                mma16816(o[np * 2],     pl, vh[0], vh[1]);
                mma16816(o[np * 2 + 1], pl, vh[2], vh[3]);
                mma16816(o[np * 2],     ph, vl[0], vl[1]);
                mma16816(o[np * 2 + 1], ph, vl[2], vl[3]);
            }
        }
    }

    // ---- finalize: write bf16 hi/lo ctx in [B,L,D] ----
    l0 += __shfl_xor_sync(0xffffffffu, l0, 1);
    l0 += __shfl_xor_sync(0xffffffffu, l0, 2);
    l1 += __shfl_xor_sync(0xffffffffu, l1, 1);
    l1 += __shfl_xor_sync(0xffffffffu, l1, 2);
    float i0 = 1.f / l0, i1 = 1.f / l1;
    int qrow = qt * 128 + w * 16 + (lane >> 2);
    size_t r0 = (size_t)b * Lc + qrow;
#pragma unroll
    for (int nt = 0; nt < 8; nt++) {
        int cc = h * HDc + nt * 8 + (lane & 3) * 2;
#pragma unroll
        for (int rr = 0; rr < 2; rr++) {
            float va0 = (rr ? o[nt][2] * i1 : o[nt][0] * i0);
            float va1 = (rr ? o[nt][3] * i1 : o[nt][1] * i0);
            size_t idx = (r0 + rr * 8) * Dc + cc;
            __nv_bfloat16 ha = __float2bfloat16(va0), hb = __float2bfloat16(va1);
            *(__nv_bfloat162*)(g_CXh + idx) = __halves2bfloat162(ha, hb);
            *(__nv_bfloat162*)(g_CXl + idx) = __halves2bfloat162(
                __float2bfloat16(va0 - __bfloat162float(ha)),
                __float2bfloat16(va1 - __bfloat162float(hb)));
        }
    }
}

// ---------------------------------------------------------------------------
extern "C" void kernel_launch(void* const* d_in, const int* in_sizes, int n_in,
                              void* d_out, int out_size) {
    const float* q  = (const float*)d_in[0];
    const float* k  = (const float*)d_in[1];
    const float* v  = (const float*)d_in[2];
    const float* Wq = (const float*)d_in[4];
    const float* bq = (const float*)d_in[5];
    const float* Wk = (const float*)d_in[6];
    const float* bk = (const float*)d_in[7];
    const float* Wv = (const float*)d_in[8];
    const float* bv = (const float*)d_in[9];
    const float* Wo = (const float*)d_in[10];
    const float* bo = (const float*)d_in[11];
    float* out = (float*)d_out;

    __nv_bfloat16 *Qh, *Ql, *Kh, *Kl, *Vh, *Vl, *CXh, *CXl;
    cudaGetSymbolAddress((void**)&Qh, g_Qh);
    cudaGetSymbolAddress((void**)&Ql, g_Ql);
    cudaGetSymbolAddress((void**)&Kh, g_Kh);
    cudaGetSymbolAddress((void**)&Kl, g_Kl);
    cudaGetSymbolAddress((void**)&Vh, g_Vh);
    cudaGetSymbolAddress((void**)&Vl, g_Vl);
    cudaGetSymbolAddress((void**)&CXh, g_CXh);
    cudaGetSymbolAddress((void**)&CXl, g_CXl);

    const int gsmem = 55296;
    const int fsmem = 73728;
    cudaFuncSetAttribute(gemm_mma<0>, cudaFuncAttributeMaxDynamicSharedMemorySize, gsmem);
    cudaFuncSetAttribute(gemm_mma<1>, cudaFuncAttributeMaxDynamicSharedMemorySize, gsmem);
    cudaFuncSetAttribute(flash_mma, cudaFuncAttributeMaxDynamicSharedMemorySize, fsmem);

    dim3 grd_gemm(Dc / 64, BL / 128);  // 8 x 64

    gemm_mma<1><<<grd_gemm, 256, gsmem>>>(q, nullptr, nullptr, Wq, bq, nullptr, Qh, Ql);
    gemm_mma<1><<<grd_gemm, 256, gsmem>>>(k, nullptr, nullptr, Wk, bk, nullptr, Kh, Kl);
    gemm_mma<1><<<grd_gemm, 256, gsmem>>>(v, nullptr, nullptr, Wv, bv, nullptr, Vh, Vl);

    dim3 grd_fa(Lc / 128, Hc, Bc);     // 16 x 8 x 4
    flash_mma<<<grd_fa, 256, fsmem>>>();

    gemm_mma<0><<<grd_gemm, 256, gsmem>>>(nullptr, CXh, CXl, Wo, bo, out, nullptr, nullptr);
}